// round 14
// baseline (speedup 1.0000x reference)
#include <cuda_runtime.h>
#include <math_constants.h>

#define K_LEN 1024
#define I_LEN 8192
#define DIM   128
#define FULLM 0xffffffffu

#define NB   64      // row bands (CTAs)
#define BR   16      // rows per band
#define NCH  16      // column chunks
#define CW   512     // columns per chunk (4 warps x 4 cols/lane)
#define DTH  128     // DP threads per CTA

// Scratch (alloc-free rule: __device__ globals)
__device__ float g_C[K_LEN * I_LEN];       // 32 MB cost matrix
__device__ float g_k2[K_LEN];
__device__ float g_x2[I_LEN];
__device__ float g_row[NB][I_LEN];         // bottom-row D of each band
__device__ unsigned g_flag[NB][NCH];       // chunk-done flags

// ---------------------------------------------------------------------------
// Kernel 1: squared row norms + zero the wavefront flags.
// ---------------------------------------------------------------------------
__global__ void norms_kernel(const float* __restrict__ kern,
                             const float* __restrict__ x) {
    int gtid = blockIdx.x * blockDim.x + threadIdx.x;
    if (gtid < NB * NCH) ((unsigned*)g_flag)[gtid] = 0u;

    int warp = gtid >> 5;
    int lane = threadIdx.x & 31;
    if (warp >= K_LEN + I_LEN) return;
    const float* row = (warp < K_LEN) ? (kern + warp * DIM)
                                      : (x + (warp - K_LEN) * DIM);
    float4 v = ((const float4*)row)[lane];
    float s = v.x * v.x + v.y * v.y + v.z * v.z + v.w * v.w;
#pragma unroll
    for (int off = 16; off; off >>= 1) s += __shfl_xor_sync(FULLM, s, off);
    if (lane == 0) {
        if (warp < K_LEN) g_k2[warp] = s;
        else              g_x2[warp - K_LEN] = s;
    }
}

// ---------------------------------------------------------------------------
// Kernel 2: C[m][n] = max(k2[m] + x2[n] - 2*<kern_m, x_n>, 0)   (R7 version)
// ---------------------------------------------------------------------------
#define BM 128
#define BN 128
#define BK 8

__global__ __launch_bounds__(256, 2) void cost_gemm(const float* __restrict__ A,
                                                    const float* __restrict__ B) {
    __shared__ float As[2][BK][BM + 4];
    __shared__ float Bs[2][BK][BN + 4];
    const int tid = threadIdx.x;
    const int m0 = blockIdx.y * BM;
    const int n0 = blockIdx.x * BN;
    const int lr = tid >> 1;
    const int lc = (tid & 1) * 4;
    const int tx = tid & 15;
    const int ty = tid >> 4;

    float acc[8][8];
#pragma unroll
    for (int i = 0; i < 8; i++)
#pragma unroll
        for (int j = 0; j < 8; j++) acc[i][j] = 0.0f;

    {
        float4 va = *(const float4*)(A + (size_t)(m0 + lr) * DIM + lc);
        float4 vb = *(const float4*)(B + (size_t)(n0 + lr) * DIM + lc);
        As[0][lc + 0][lr] = va.x; As[0][lc + 1][lr] = va.y;
        As[0][lc + 2][lr] = va.z; As[0][lc + 3][lr] = va.w;
        Bs[0][lc + 0][lr] = vb.x; Bs[0][lc + 1][lr] = vb.y;
        Bs[0][lc + 2][lr] = vb.z; Bs[0][lc + 3][lr] = vb.w;
    }
    __syncthreads();

    int buf = 0;
    for (int k0 = 0; k0 < DIM; k0 += BK) {
        const bool has_next = (k0 + BK < DIM);
        float4 na, nb;
        if (has_next) {
            na = *(const float4*)(A + (size_t)(m0 + lr) * DIM + k0 + BK + lc);
            nb = *(const float4*)(B + (size_t)(n0 + lr) * DIM + k0 + BK + lc);
        }
#pragma unroll
        for (int k = 0; k < BK; k++) {
            float a[8], b[8];
            *(float4*)(a)     = *(const float4*)&As[buf][k][ty * 8];
            *(float4*)(a + 4) = *(const float4*)&As[buf][k][ty * 8 + 4];
            *(float4*)(b)     = *(const float4*)&Bs[buf][k][tx * 8];
            *(float4*)(b + 4) = *(const float4*)&Bs[buf][k][tx * 8 + 4];
#pragma unroll
            for (int i = 0; i < 8; i++)
#pragma unroll
                for (int j = 0; j < 8; j++)
                    acc[i][j] += a[i] * b[j];
        }
        if (has_next) {
            const int nbuf = buf ^ 1;
            As[nbuf][lc + 0][lr] = na.x; As[nbuf][lc + 1][lr] = na.y;
            As[nbuf][lc + 2][lr] = na.z; As[nbuf][lc + 3][lr] = na.w;
            Bs[nbuf][lc + 0][lr] = nb.x; Bs[nbuf][lc + 1][lr] = nb.y;
            Bs[nbuf][lc + 2][lr] = nb.z; Bs[nbuf][lc + 3][lr] = nb.w;
            __syncthreads();
            buf = nbuf;
        }
    }

    float x2v[8];
#pragma unroll
    for (int j = 0; j < 8; j++) x2v[j] = g_x2[n0 + tx * 8 + j];
#pragma unroll
    for (int i = 0; i < 8; i++) {
        const int m = m0 + ty * 8 + i;
        const float k2 = g_k2[m];
        float4 o0, o1;
        o0.x = fmaxf(k2 + x2v[0] - 2.0f * acc[i][0], 0.0f);
        o0.y = fmaxf(k2 + x2v[1] - 2.0f * acc[i][1], 0.0f);
        o0.z = fmaxf(k2 + x2v[2] - 2.0f * acc[i][2], 0.0f);
        o0.w = fmaxf(k2 + x2v[3] - 2.0f * acc[i][3], 0.0f);
        o1.x = fmaxf(k2 + x2v[4] - 2.0f * acc[i][4], 0.0f);
        o1.y = fmaxf(k2 + x2v[5] - 2.0f * acc[i][5], 0.0f);
        o1.z = fmaxf(k2 + x2v[6] - 2.0f * acc[i][6], 0.0f);
        o1.w = fmaxf(k2 + x2v[7] - 2.0f * acc[i][7], 0.0f);
        float* dst = g_C + (size_t)m * I_LEN + n0 + tx * 8;
        *(float4*)(dst)     = o0;
        *(float4*)(dst + 4) = o1;
    }
}

// ---------------------------------------------------------------------------
// Kernel 3: block-wavefront DTW DP, ONE barrier per row.
// Identity used: lane 0's Din = D[r][warp_left-1], which is exactly the
// dleft that lane needs at row r+1 (for warp 0 lane 0: Din = Dlv, the chunk
// left boundary — also the correct diagonal). Lanes>0 get dleft by shfl_up
// of their neighbor's previous-row D3. So sh_bound and the second barrier
// are deleted; shC/shE are ping-ponged per row parity.
// ---------------------------------------------------------------------------
__global__ __launch_bounds__(DTH, 1) void dtw_wave(float* __restrict__ out,
                                                   int out_size) {
    __shared__ float shC[2][4], shE[2][4];
    __shared__ float Dl[2][BR];      // left-boundary D per row, chunk ping-pong
    const float INF = CUDART_INF_F;
    const int b    = blockIdx.x;
    const int tid  = threadIdx.x;
    const int lane = tid & 31;
    const int w    = tid >> 5;

    if (b == 0)
        for (int i = tid; i < out_size; i += DTH)
            if (i > 0) out[i] = 0.0f;
    if (tid < BR) Dl[0][tid] = INF;   // chunk 0 has no left neighbor

    float res = INF;

    for (int j = 0; j < NCH; j++) {
        const int sel = j & 1;
        if (b > 0 && tid == 0) {
            unsigned v;
            do {
                asm volatile("ld.acquire.gpu.global.u32 %0, [%1];"
                             : "=r"(v) : "l"(&g_flag[b - 1][j]));
            } while (!v);
        }
        __syncthreads();   // flag visible; Dl/sh buffers from prev chunk safe

        const int colbase = j * CW + 4 * tid;

        // top boundary (row above the band)
        float Dp0, Dp1, Dp2, Dp3;
        if (b > 0) {
            float4 tv = *(const float4*)(&g_row[b - 1][colbase]);
            Dp0 = tv.x; Dp1 = tv.y; Dp2 = tv.z; Dp3 = tv.w;
        } else {
            Dp0 = Dp1 = Dp2 = Dp3 = INF;
        }
        float lastD3 = Dp3;

        // dinPrev: the dleft for row 0 at lane 0 of each warp
        float dinPrev = INF;
        if (lane == 0) {
            if (w == 0) {
                if (b > 0) dinPrev = (j > 0) ? g_row[b - 1][j * CW - 1] : INF;
                else       dinPrev = (j == 0) ? 0.0f : INF;   // D[-1][-1]=0
            } else {
                dinPrev = (b > 0) ? g_row[b - 1][j * CW + 128 * w - 1] : INF;
            }
        }

        const float* cbase = g_C + (size_t)(b * BR) * I_LEN + colbase;
        float4 cc = *(const float4*)cbase;

        for (int r = 0; r < BR; r++) {
            const int par = r & 1;
            float4 pf;
            if (r + 1 < BR)
                pf = *(const float4*)(cbase + (size_t)(r + 1) * I_LEN);

            float dleft = __shfl_up_sync(FULLM, lastD3, 1);
            if (lane == 0) dleft = dinPrev;

            const float c0 = cc.x, c1 = cc.y, c2 = cc.z, c3 = cc.w;
            float e0 = fminf(dleft, Dp0) + c0;
            float e1 = fminf(Dp0, Dp1) + c1;
            float e2 = fminf(Dp1, Dp2) + c2;
            float e3 = fminf(Dp2, Dp3) + c3;

            float Cl = c0 + c1 + c2 + c3;
            float El = e0;
            El = fminf(El + c1, e1);
            El = fminf(El + c2, e2);
            El = fminf(El + c3, e3);

#pragma unroll
            for (int off = 1; off < 32; off <<= 1) {
                float Cu = __shfl_up_sync(FULLM, Cl, off);
                float Eu = __shfl_up_sync(FULLM, El, off);
                if (lane >= off) {
                    El = fminf(Eu + Cl, El);
                    Cl = Cu + Cl;
                }
            }
            if (lane == 31) { shC[par][w] = Cl; shE[par][w] = El; }
            __syncthreads();   // the ONLY barrier in the row loop

            float wC = 0.0f, wE = INF;
#pragma unroll
            for (int k = 0; k < 3; k++) {
                if (k < w) {
                    wE = fminf(wE + shC[par][k], shE[par][k]);
                    wC = wC + shC[par][k];
                }
            }
            float exC = __shfl_up_sync(FULLM, Cl, 1);
            float exE = __shfl_up_sync(FULLM, El, 1);
            if (lane == 0) { exC = 0.0f; exE = INF; }

            float Dlv = Dl[sel][r];                 // D[row][chunk_left - 1]
            float Cex = wC + exC;
            float Eex = fminf(wE + exC, exE);
            float Din = fminf(Eex, Dlv + Cex);      // = D[r][4*tid - 1]

            float D0 = fminf(Din + c0, e0);
            float D1 = fminf(D0 + c1, e1);
            float D2 = fminf(D1 + c2, e2);
            float D3 = fminf(D2 + c3, e3);

            if (tid == DTH - 1) Dl[sel ^ 1][r] = D3; // left bound, next chunk
            if (r == BR - 1) {
                if (b < NB - 1)
                    *(float4*)(&g_row[b][colbase]) = make_float4(D0, D1, D2, D3);
                res = D3;
            }

            dinPrev = Din;       // lane 0's dleft for the next row
            lastD3 = D3;
            Dp0 = D0; Dp1 = D1; Dp2 = D2; Dp3 = D3;
            cc = pf;
        }
        __syncthreads();         // g_row / Dl writes complete

        if (b < NB - 1) {
            __threadfence();
            if (tid == 0)
                asm volatile("st.release.gpu.global.u32 [%0], %1;"
                             :: "l"(&g_flag[b][j]), "r"(1u));
        }
    }

    if (b == NB - 1 && tid == DTH - 1) out[0] = res;
}

// ---------------------------------------------------------------------------
extern "C" void kernel_launch(void* const* d_in, const int* in_sizes, int n_in,
                              void* d_out, int out_size) {
    const float* kern = (const float*)d_in[0];
    const float* x    = (const float*)d_in[1];
    if (n_in >= 2 && in_sizes[0] == I_LEN * DIM && in_sizes[1] == K_LEN * DIM) {
        kern = (const float*)d_in[1];
        x    = (const float*)d_in[0];
    }

    int nwarp_rows = K_LEN + I_LEN;
    norms_kernel<<<(nwarp_rows + 7) / 8, 256>>>(kern, x);

    dim3 grid(I_LEN / BN, K_LEN / BM);
    cost_gemm<<<grid, 256>>>(kern, x);

    dtw_wave<<<NB, DTH>>>((float*)d_out, out_size);
}

// round 15
// speedup vs baseline: 1.1104x; 1.1104x over previous
#include <cuda_runtime.h>
#include <math_constants.h>

#define K_LEN 1024
#define I_LEN 8192
#define DIM   128
#define FULLM 0xffffffffu

#define NB   64      // row bands (CTAs)
#define BR   16      // rows per band
#define NCH  16      // column chunks
#define CW   512     // columns per chunk (4 warps x 4 cols/lane)
#define DTH  128     // DP threads per CTA

// Scratch (alloc-free rule: __device__ globals)
__device__ float g_C[K_LEN * I_LEN];       // cost matrix -> row-cumsum S (in place)
__device__ float g_k2[K_LEN];
__device__ float g_x2[I_LEN];
__device__ float g_row[NB][I_LEN];         // bottom-row D of each band
__device__ unsigned g_flag[NB][NCH];       // chunk-done flags

// ---------------------------------------------------------------------------
// Kernel 1: squared row norms + zero the wavefront flags.
// ---------------------------------------------------------------------------
__global__ void norms_kernel(const float* __restrict__ kern,
                             const float* __restrict__ x) {
    int gtid = blockIdx.x * blockDim.x + threadIdx.x;
    if (gtid < NB * NCH) ((unsigned*)g_flag)[gtid] = 0u;

    int warp = gtid >> 5;
    int lane = threadIdx.x & 31;
    if (warp >= K_LEN + I_LEN) return;
    const float* row = (warp < K_LEN) ? (kern + warp * DIM)
                                      : (x + (warp - K_LEN) * DIM);
    float4 v = ((const float4*)row)[lane];
    float s = v.x * v.x + v.y * v.y + v.z * v.z + v.w * v.w;
#pragma unroll
    for (int off = 16; off; off >>= 1) s += __shfl_xor_sync(FULLM, s, off);
    if (lane == 0) {
        if (warp < K_LEN) g_k2[warp] = s;
        else              g_x2[warp - K_LEN] = s;
    }
}

// ---------------------------------------------------------------------------
// Kernel 2: C[m][n] = max(k2[m] + x2[n] - 2*<kern_m, x_n>, 0)   (R7 version)
// ---------------------------------------------------------------------------
#define BM 128
#define BN 128
#define BK 8

__global__ __launch_bounds__(256, 2) void cost_gemm(const float* __restrict__ A,
                                                    const float* __restrict__ B) {
    __shared__ float As[2][BK][BM + 4];
    __shared__ float Bs[2][BK][BN + 4];
    const int tid = threadIdx.x;
    const int m0 = blockIdx.y * BM;
    const int n0 = blockIdx.x * BN;
    const int lr = tid >> 1;
    const int lc = (tid & 1) * 4;
    const int tx = tid & 15;
    const int ty = tid >> 4;

    float acc[8][8];
#pragma unroll
    for (int i = 0; i < 8; i++)
#pragma unroll
        for (int j = 0; j < 8; j++) acc[i][j] = 0.0f;

    {
        float4 va = *(const float4*)(A + (size_t)(m0 + lr) * DIM + lc);
        float4 vb = *(const float4*)(B + (size_t)(n0 + lr) * DIM + lc);
        As[0][lc + 0][lr] = va.x; As[0][lc + 1][lr] = va.y;
        As[0][lc + 2][lr] = va.z; As[0][lc + 3][lr] = va.w;
        Bs[0][lc + 0][lr] = vb.x; Bs[0][lc + 1][lr] = vb.y;
        Bs[0][lc + 2][lr] = vb.z; Bs[0][lc + 3][lr] = vb.w;
    }
    __syncthreads();

    int buf = 0;
    for (int k0 = 0; k0 < DIM; k0 += BK) {
        const bool has_next = (k0 + BK < DIM);
        float4 na, nb;
        if (has_next) {
            na = *(const float4*)(A + (size_t)(m0 + lr) * DIM + k0 + BK + lc);
            nb = *(const float4*)(B + (size_t)(n0 + lr) * DIM + k0 + BK + lc);
        }
#pragma unroll
        for (int k = 0; k < BK; k++) {
            float a[8], b[8];
            *(float4*)(a)     = *(const float4*)&As[buf][k][ty * 8];
            *(float4*)(a + 4) = *(const float4*)&As[buf][k][ty * 8 + 4];
            *(float4*)(b)     = *(const float4*)&Bs[buf][k][tx * 8];
            *(float4*)(b + 4) = *(const float4*)&Bs[buf][k][tx * 8 + 4];
#pragma unroll
            for (int i = 0; i < 8; i++)
#pragma unroll
                for (int j = 0; j < 8; j++)
                    acc[i][j] += a[i] * b[j];
        }
        if (has_next) {
            const int nbuf = buf ^ 1;
            As[nbuf][lc + 0][lr] = na.x; As[nbuf][lc + 1][lr] = na.y;
            As[nbuf][lc + 2][lr] = na.z; As[nbuf][lc + 3][lr] = na.w;
            Bs[nbuf][lc + 0][lr] = nb.x; Bs[nbuf][lc + 1][lr] = nb.y;
            Bs[nbuf][lc + 2][lr] = nb.z; Bs[nbuf][lc + 3][lr] = nb.w;
            __syncthreads();
            buf = nbuf;
        }
    }

    float x2v[8];
#pragma unroll
    for (int j = 0; j < 8; j++) x2v[j] = g_x2[n0 + tx * 8 + j];
#pragma unroll
    for (int i = 0; i < 8; i++) {
        const int m = m0 + ty * 8 + i;
        const float k2 = g_k2[m];
        float4 o0, o1;
        o0.x = fmaxf(k2 + x2v[0] - 2.0f * acc[i][0], 0.0f);
        o0.y = fmaxf(k2 + x2v[1] - 2.0f * acc[i][1], 0.0f);
        o0.z = fmaxf(k2 + x2v[2] - 2.0f * acc[i][2], 0.0f);
        o0.w = fmaxf(k2 + x2v[3] - 2.0f * acc[i][3], 0.0f);
        o1.x = fmaxf(k2 + x2v[4] - 2.0f * acc[i][4], 0.0f);
        o1.y = fmaxf(k2 + x2v[5] - 2.0f * acc[i][5], 0.0f);
        o1.z = fmaxf(k2 + x2v[6] - 2.0f * acc[i][6], 0.0f);
        o1.w = fmaxf(k2 + x2v[7] - 2.0f * acc[i][7], 0.0f);
        float* dst = g_C + (size_t)m * I_LEN + n0 + tx * 8;
        *(float4*)(dst)     = o0;
        *(float4*)(dst + 4) = o1;
    }
}

// ---------------------------------------------------------------------------
// Kernel 2.5: in-place row-wise cumsum (R10-validated). One CTA per row.
// ---------------------------------------------------------------------------
__global__ __launch_bounds__(256) void rowcumsum() {
    __shared__ float part[8];
    const int r    = blockIdx.x;
    const int tid  = threadIdx.x;
    const int lane = tid & 31;
    const int wid  = tid >> 5;
    float4* rowp = (float4*)(g_C + (size_t)r * I_LEN + tid * 32);

    float4 V[8];
#pragma unroll
    for (int i = 0; i < 8; i++) V[i] = rowp[i];
    float* v = (float*)V;
#pragma unroll
    for (int j = 1; j < 32; j++) v[j] = v[j] + v[j - 1];

    float W = v[31];
#pragma unroll
    for (int off = 1; off < 32; off <<= 1) {
        float u = __shfl_up_sync(FULLM, W, off);
        if (lane >= off) W += u;
    }
    if (lane == 31) part[wid] = W;
    float ex = __shfl_up_sync(FULLM, W, 1);
    if (lane == 0) ex = 0.0f;
    __syncthreads();
    float woff = 0.0f;
#pragma unroll
    for (int k = 0; k < 7; k++)
        if (k < wid) woff += part[k];
    float off0 = woff + ex;
#pragma unroll
    for (int j = 0; j < 32; j++) v[j] += off0;
#pragma unroll
    for (int i = 0; i < 8; i++) rowp[i] = V[i];
}

// ---------------------------------------------------------------------------
// Kernel 3: block-wavefront DTW DP over precomputed S = rowcumsum(c).
// Per row (R12 skeleton, 2 barriers, sh_bound):
//   z[j] = min(Dprev[j-1], Dprev[j]) - S[j-1]          (costs cancel)
//   F[j] = min(F[j-1], z[j])   (single-value min-scan: local cummin +
//                               5-SHFL warp scan + tiny cross-warp combine)
//   D[j] = S[j] + F[j]                                  (parallel apply)
// Chunk carry: Fl (= F at chunk's last col) and Dl (= D, for the diagonal).
// ---------------------------------------------------------------------------
__global__ __launch_bounds__(DTH, 1) void dtw_wave(float* __restrict__ out,
                                                   int out_size) {
    __shared__ float sh_bound[DTH];
    __shared__ float sh_part[4];
    __shared__ float Dl[2][BR];      // D at chunk-left-1 per row (diag source)
    __shared__ float Fl[2][BR];      // F carry at chunk-left-1 per row
    const float INF = CUDART_INF_F;
    const int b    = blockIdx.x;
    const int tid  = threadIdx.x;
    const int lane = tid & 31;
    const int w    = tid >> 5;

    if (b == 0)
        for (int i = tid; i < out_size; i += DTH)
            if (i > 0) out[i] = 0.0f;
    if (tid < BR) { Dl[0][tid] = INF; Fl[0][tid] = INF; }

    float res = INF;

    for (int j = 0; j < NCH; j++) {
        const int sel = j & 1;
        if (b > 0 && tid == 0) {
            unsigned v;
            do {
                asm volatile("ld.acquire.gpu.global.u32 %0, [%1];"
                             : "=r"(v) : "l"(&g_flag[b - 1][j]));
            } while (!v);
        }
        __syncthreads();

        const int colbase = j * CW + 4 * tid;

        // top boundary (row above the band)
        float Dp0, Dp1, Dp2, Dp3;
        if (b > 0) {
            float4 tv = *(const float4*)(&g_row[b - 1][colbase]);
            Dp0 = tv.x; Dp1 = tv.y; Dp2 = tv.z; Dp3 = tv.w;
        } else {
            Dp0 = Dp1 = Dp2 = Dp3 = INF;
        }
        // top-left diagonal value for thread 0, row 0
        float dlc;
        if (b > 0) dlc = (j > 0) ? g_row[b - 1][j * CW - 1] : INF;
        else       dlc = (j == 0) ? 0.0f : INF;   // D[-1][-1] = 0
        sh_bound[tid] = Dp3;
        __syncthreads();

        const float* cbase = g_C + (size_t)(b * BR) * I_LEN + colbase;
        float4 cc = *(const float4*)cbase;                 // S values, this row
        float sm1 = 0.0f;                                  // S[colbase-1], lane 0
        if (lane == 0 && colbase > 0) sm1 = __ldg(cbase - 1);

        for (int r = 0; r < BR; r++) {
            float4 pf;
            float sm1_nx = 0.0f;
            if (r + 1 < BR) {
                const float* nrow = cbase + (size_t)(r + 1) * I_LEN;
                pf = *(const float4*)nrow;
                if (lane == 0 && colbase > 0) sm1_nx = __ldg(nrow - 1);
            }

            float dleft = (tid == 0) ? dlc : sh_bound[tid - 1];
            // S[j-1] for the first element of this thread
            float Sm1 = __shfl_up_sync(FULLM, cc.w, 1);
            if (lane == 0) Sm1 = sm1;

            // z values (costs cancel against cumsum)
            float z0 = fminf(dleft, Dp0) - Sm1;
            float z1 = fminf(Dp0, Dp1) - cc.x;
            float z2 = fminf(Dp1, Dp2) - cc.y;
            float z3 = fminf(Dp2, Dp3) - cc.z;
            float pz0 = z0;
            float pz1 = fminf(pz0, z1);
            float pz2 = fminf(pz1, z2);
            float pz3 = fminf(pz2, z3);

            // single-value warp min-scan
            float W = pz3;
#pragma unroll
            for (int off = 1; off < 32; off <<= 1) {
                float u = __shfl_up_sync(FULLM, W, off);
                if (lane >= off) W = fminf(W, u);
            }
            if (lane == 31) sh_part[w] = W;
            __syncthreads();

            float wmin = INF;
#pragma unroll
            for (int k = 0; k < 3; k++)
                if (k < w) wmin = fminf(wmin, sh_part[k]);
            float ex = __shfl_up_sync(FULLM, W, 1);
            if (lane == 0) ex = INF;

            float Dlv = Dl[sel][r];                 // D[row][chunk_left-1]
            float Flv = Fl[sel][r];                 // F carry from prev chunk
            float Min = fminf(fminf(wmin, ex), Flv);

            float F0 = fminf(Min, pz0);
            float F1 = fminf(Min, pz1);
            float F2 = fminf(Min, pz2);
            float F3 = fminf(Min, pz3);
            float D0 = cc.x + F0;
            float D1 = cc.y + F1;
            float D2 = cc.z + F2;
            float D3 = cc.w + F3;

            dlc = Dlv;                               // diag for next row (tid 0)
            if (tid == DTH - 1) {
                Dl[sel ^ 1][r] = D3;                 // boundary for next chunk
                Fl[sel ^ 1][r] = F3;
            }
            if (r == BR - 1) {
                if (b < NB - 1)
                    *(float4*)(&g_row[b][colbase]) =
                        make_float4(D0, D1, D2, D3);
                res = D3;
            }
            sh_bound[tid] = D3;
            Dp0 = D0; Dp1 = D1; Dp2 = D2; Dp3 = D3;
            cc = pf;
            sm1 = sm1_nx;
            __syncthreads();
        }

        if (b < NB - 1) {
            __threadfence();
            if (tid == 0)
                asm volatile("st.release.gpu.global.u32 [%0], %1;"
                             :: "l"(&g_flag[b][j]), "r"(1u));
        }
    }

    if (b == NB - 1 && tid == DTH - 1) out[0] = res;
}

// ---------------------------------------------------------------------------
extern "C" void kernel_launch(void* const* d_in, const int* in_sizes, int n_in,
                              void* d_out, int out_size) {
    const float* kern = (const float*)d_in[0];
    const float* x    = (const float*)d_in[1];
    if (n_in >= 2 && in_sizes[0] == I_LEN * DIM && in_sizes[1] == K_LEN * DIM) {
        kern = (const float*)d_in[1];
        x    = (const float*)d_in[0];
    }

    int nwarp_rows = K_LEN + I_LEN;
    norms_kernel<<<(nwarp_rows + 7) / 8, 256>>>(kern, x);

    dim3 grid(I_LEN / BN, K_LEN / BM);
    cost_gemm<<<grid, 256>>>(kern, x);

    rowcumsum<<<K_LEN, 256>>>();

    dtw_wave<<<NB, DTH>>>((float*)d_out, out_size);
}